// round 6
// baseline (speedup 1.0000x reference)
#include <cuda_runtime.h>
#include <cuda_fp16.h>
#include <cstdint>

#define BB 4
#define HH 8
#define LQ 256
#define LK 256
#define DKD 64
#define BHN (BB*HH)               // 32
#define NQROWS (BHN*LQ)           // 8192
#define OUT_ELEMS (NQROWS*DKD)    // 524288

#define PSTRIDE 258               // p_s row stride (floats)
#define VSTRIDE 68                // v tile row stride (floats, float4-aligned)

// Scratch (no cudaMalloc allowed)
__device__ float    g_qp[NQROWS * DKD];            // [bh*Lq + q][d] f32
__device__ uint32_t g_kph[BHN * DKD * (LK / 2)];   // [bh][d][pair] f16x2 (k-pairs)

__device__ __forceinline__ uint32_t tanh2(uint32_t x) {
    uint32_t y;
    asm("tanh.approx.f16x2 %0, %1;" : "=r"(y) : "r"(x));
    return y;
}
__device__ __forceinline__ uint32_t hadd2u(uint32_t a, uint32_t b) {
    uint32_t d;
    asm("add.f16x2 %0, %1, %2;" : "=r"(d) : "r"(a), "r"(b));
    return d;
}
__device__ __forceinline__ uint32_t hfma2u(uint32_t a, uint32_t b, uint32_t c) {
    uint32_t d;
    asm("fma.rn.f16x2 %0, %1, %2, %3;" : "=r"(d) : "r"(a), "r"(b), "r"(c));
    return d;
}
__device__ __forceinline__ uint32_t pack2(float lo, float hi) {
    __half2 h = __floats2half2_rn(lo, hi);
    return *reinterpret_cast<uint32_t*>(&h);
}
__device__ __forceinline__ uint32_t dup2(float x) { return pack2(x, x); }
__device__ __forceinline__ float2 unpack2(uint32_t v) {
    __half2 h = *reinterpret_cast<__half2*>(&v);
    return __half22float2(h);
}

// ---------------------------------------------------------------------------
// Kernel 1: both projections. blocks [0,128): qp rows (f32 row-major).
// [128,256): kp rows -> g_kph packed f16x2 k-pairs, [bh][d][pair].
// ---------------------------------------------------------------------------
__global__ void proj_kernel(const float* __restrict__ xq,
                            const float* __restrict__ xk,
                            const float* __restrict__ Wq,
                            const float* __restrict__ bq,
                            const float* __restrict__ Wk,
                            const float* __restrict__ bk)
{
    __shared__ float Ws[DKD][DKD + 1];
    __shared__ float xs[64][DKD];

    const bool is_k = blockIdx.x >= 128;
    const int  blk  = is_k ? (blockIdx.x - 128) : blockIdx.x;
    const float* x  = is_k ? xk : xq;
    const float* W  = is_k ? Wk : Wq;
    const float* bi = is_k ? bk : bq;

    const int tid  = threadIdx.x;        // 0..511
    const int row0 = blk * 64;

    for (int i = tid; i < DKD * DKD; i += 512)
        Ws[i >> 6][i & 63] = W[i];
    for (int i = tid; i < 64 * DKD; i += 512)
        xs[i >> 6][i & 63] = x[row0 * DKD + i];
    __syncthreads();

    const int e  = tid & 63;
    const int rg = tid >> 6;             // 0..7 -> rows rg*8 .. rg*8+7
    const float b = bi[e];

    float acc[8];
#pragma unroll
    for (int j = 0; j < 8; j++) acc[j] = 0.f;

#pragma unroll
    for (int d = 0; d < DKD; d++) {
        const float w = Ws[e][d];
#pragma unroll
        for (int j = 0; j < 8; j++)
            acc[j] += w * xs[rg * 8 + j][d];
    }

    if (!is_k) {
#pragma unroll
        for (int j = 0; j < 8; j++)
            g_qp[(row0 + rg * 8 + j) * DKD + e] = acc[j] + b;   // coalesced
    } else {
        const int bh = row0 >> 8;
        const int k0 = (row0 & 255) + rg * 8;
        uint4 pk;
        pk.x = pack2(acc[0] + b, acc[1] + b);
        pk.y = pack2(acc[2] + b, acc[3] + b);
        pk.z = pack2(acc[4] + b, acc[5] + b);
        pk.w = pack2(acc[6] + b, acc[7] + b);
        *(uint4*)(g_kph + bh * (DKD * (LK / 2)) + e * (LK / 2) + (k0 >> 1)) = pk;
    }
}

// ---------------------------------------------------------------------------
// Kernel 2: raw scores, K-split. Grid 2048 = 32 bh x 32 q-tiles x 2 k-chunks.
// Block 128 thr (4 warps), high occupancy via __launch_bounds__(128,12).
// CTA = 8 q rows x 128 k. Warp = q-pair; lane = 4 adjacent k (2 f16x2 pairs).
// Per d: LDS.64 kp + LDS.64 q + LDS.32 w + 4x(HADD2,TANH2,HFMA2) = 15 issues.
// Raw (un-normalized, vs_b-free) scores -> attn buffer.
// ---------------------------------------------------------------------------
__global__ void __launch_bounds__(128, 12)
score_kernel(const float* __restrict__ vs_w,
             float* __restrict__ raw)
{
    __shared__ uint32_t kph[DKD * 64];   // [d][pair] 16KB
    __shared__ uint32_t qh2[DKD * 8];    // [d][qr] dup f16x2
    __shared__ uint32_t vswh2[DKD];

    const int tid  = threadIdx.x;        // 0..127
    const int lane = tid & 31;
    const int warp = tid >> 5;           // 0..3
    const int bh   = blockIdx.x >> 6;
    const int qt   = (blockIdx.x >> 1) & 31;
    const int c    = blockIdx.x & 1;     // k-chunk
    const int q0   = qt * 8;

    if (tid < DKD) vswh2[tid] = dup2(vs_w[tid]);
    {   // qh2[d][qr] duplicated halves
        const int qr = tid & 7;
        const int d4 = tid >> 3;         // 0..15
        const float4 qv = *(const float4*)(g_qp + (bh * LQ + q0 + qr) * DKD + d4 * 4);
        qh2[(d4 * 4 + 0) * 8 + qr] = dup2(qv.x);
        qh2[(d4 * 4 + 1) * 8 + qr] = dup2(qv.y);
        qh2[(d4 * 4 + 2) * 8 + qr] = dup2(qv.z);
        qh2[(d4 * 4 + 3) * 8 + qr] = dup2(qv.w);
    }
    {   // stage g_kph chunk -> kph[d][64 pairs]
        const uint4* src = (const uint4*)(g_kph + bh * (DKD * (LK / 2)));
        uint4* dst = (uint4*)kph;
#pragma unroll
        for (int t = 0; t < 8; t++) {
            const int f4 = tid + t * 128;          // 0..1023
            const int d  = f4 >> 4;
            const int p4 = f4 & 15;
            dst[f4] = src[d * 32 + c * 16 + p4];
        }
    }
    __syncthreads();

    const int qw = warp * 2;

    float sc[2][4];
#pragma unroll
    for (int j = 0; j < 2; j++)
#pragma unroll
        for (int i = 0; i < 4; i++) sc[j][i] = 0.f;

#pragma unroll
    for (int d8 = 0; d8 < 8; d8++) {     // 8-d groups: f16x2 accumulate, flush
        uint32_t a00 = 0u, a01 = 0u, a10 = 0u, a11 = 0u;
#pragma unroll
        for (int dd = 0; dd < 8; dd++) {
            const int d = d8 * 8 + dd;
            const uint2 kp = *(const uint2*)&kph[d * 64 + 2 * lane];   // LDS.64
            const uint2 q2 = *(const uint2*)&qh2[d * 8 + qw];          // LDS.64
            const uint32_t w2 = vswh2[d];                              // LDS.32
            a00 = hfma2u(w2, tanh2(hadd2u(q2.x, kp.x)), a00);
            a01 = hfma2u(w2, tanh2(hadd2u(q2.x, kp.y)), a01);
            a10 = hfma2u(w2, tanh2(hadd2u(q2.y, kp.x)), a10);
            a11 = hfma2u(w2, tanh2(hadd2u(q2.y, kp.y)), a11);
        }
        float2 f;
        f = unpack2(a00); sc[0][0] += f.x; sc[0][1] += f.y;
        f = unpack2(a01); sc[0][2] += f.x; sc[0][3] += f.y;
        f = unpack2(a10); sc[1][0] += f.x; sc[1][1] += f.y;
        f = unpack2(a11); sc[1][2] += f.x; sc[1][3] += f.y;
    }

    // lane's k = c*128 + 4*lane + {0,1,2,3}
#pragma unroll
    for (int j = 0; j < 2; j++) {
        float* dst = raw + (bh * LQ + q0 + qw + j) * LK + c * 128 + 4 * lane;
        *(float4*)dst = make_float4(sc[j][0], sc[j][1], sc[j][2], sc[j][3]);
    }
}

// ---------------------------------------------------------------------------
// Kernel 3: softmax (in-place raw -> attn) + output = attn @ v.
// Grid 512 = 32 bh x 16 q-tiles (16 rows). Block 256 thr (8 warps).
// Softmax: warp = 2 q rows, coalesced row load/store, p cached in SMEM.
// Phase 2: thread = (q = tid&15, d-group = tid>>4 -> 4 d's), v in float4 tiles.
// ---------------------------------------------------------------------------
__global__ void __launch_bounds__(256, 6)
softmax_out_kernel(const float* __restrict__ v,
                   float* __restrict__ out,
                   float* __restrict__ attn)
{
    __shared__ float p_s[16 * PSTRIDE];  // 16.5KB
    __shared__ float vv[64 * VSTRIDE];   // 17.4KB

    const int tid  = threadIdx.x;        // 0..255
    const int lane = tid & 31;
    const int warp = tid >> 5;           // 0..7
    const int bh   = blockIdx.x >> 4;
    const int q0   = (blockIdx.x & 15) * 16;

    // ---- softmax: warp handles q rows q0 + warp*2 + {0,1} ----
#pragma unroll
    for (int j = 0; j < 2; j++) {
        const int qr = warp * 2 + j;
        float* row = attn + (bh * LQ + q0 + qr) * LK;

        float x[8];
#pragma unroll
        for (int i = 0; i < 8; i++) x[i] = row[i * 32 + lane];

        float m = x[0];
#pragma unroll
        for (int i = 1; i < 8; i++) m = fmaxf(m, x[i]);
#pragma unroll
        for (int o = 16; o > 0; o >>= 1)
            m = fmaxf(m, __shfl_xor_sync(0xffffffffu, m, o));

        float p[8];
        float s = 0.f;
#pragma unroll
        for (int i = 0; i < 8; i++) { p[i] = __expf(x[i] - m); s += p[i]; }
#pragma unroll
        for (int o = 16; o > 0; o >>= 1)
            s += __shfl_xor_sync(0xffffffffu, s, o);

        const float inv = 1.0f / s;
#pragma unroll
        for (int i = 0; i < 8; i++) {
            const float pv = p[i] * inv;
            row[i * 32 + lane]                 = pv;   // in-place normalize
            p_s[qr * PSTRIDE + i * 32 + lane]  = pv;
        }
    }
    __syncthreads();

    // ---- phase 2: out[q][d] = sum_k p[q][k] * v[k][d] ----
    const int q  = tid & 15;
    const int dg = tid >> 4;             // 0..15 -> d = dg*4 .. dg*4+3

    float acc[4];
#pragma unroll
    for (int i = 0; i < 4; i++) acc[i] = 0.f;

    for (int c = 0; c < 4; c++) {        // v chunks of 64 k-rows
        if (c) __syncthreads();
        {   // stage v chunk: 1024 float4 / 256 thr = 4 each
            const float4* src = (const float4*)(v + (bh * LK + c * 64) * DKD);
#pragma unroll
            for (int t = 0; t < 4; t++) {
                const int f  = tid + t * 256;      // float4 index 0..1023
                const int k  = f >> 4;
                const int d4 = f & 15;
                *(float4*)&vv[k * VSTRIDE + d4 * 4] = src[f];
            }
        }
        __syncthreads();

#pragma unroll 4
        for (int kk = 0; kk < 64; kk++) {
            const float a   = p_s[q * PSTRIDE + c * 64 + kk];
            const float4 vk = *(const float4*)&vv[kk * VSTRIDE + dg * 4];
            acc[0] += a * vk.x; acc[1] += a * vk.y;
            acc[2] += a * vk.z; acc[3] += a * vk.w;
        }
    }

    float* od = out + (bh * LQ + q0 + q) * DKD + dg * 4;
    *(float4*)od = make_float4(acc[0], acc[1], acc[2], acc[3]);
}

// ---------------------------------------------------------------------------
extern "C" void kernel_launch(void* const* d_in, const int* in_sizes, int n_in,
                              void* d_out, int out_size)
{
    (void)in_sizes; (void)n_in; (void)out_size;
    const float* q    = (const float*)d_in[0];
    const float* k    = (const float*)d_in[1];
    const float* v    = (const float*)d_in[2];
    const float* Wq_w = (const float*)d_in[3];
    const float* Wq_b = (const float*)d_in[4];
    const float* Wk_w = (const float*)d_in[5];
    const float* Wk_b = (const float*)d_in[6];
    const float* vs_w = (const float*)d_in[7];
    // d_in[8] = vs_b: unused (softmax shift-invariance; scores not an output)

    float* out  = (float*)d_out;            // [B,H,Lq,Dk]
    float* attn = out + OUT_ELEMS;          // [B,H,Lq,Lk] (raw scores, then normalized)

    proj_kernel<<<256, 512>>>(q, k, Wq_w, Wq_b, Wk_w, Wk_b);
    score_kernel<<<2048, 128>>>(vs_w, attn);
    softmax_out_kernel<<<512, 256>>>(v, out, attn);
}

// round 7
// speedup vs baseline: 1.1468x; 1.1468x over previous
#include <cuda_runtime.h>
#include <cuda_fp16.h>
#include <cstdint>

#define BB 4
#define HH 8
#define LQ 256
#define LK 256
#define DKD 64
#define BHN (BB*HH)               // 32
#define NQROWS (BHN*LQ)           // 8192
#define OUT_ELEMS (NQROWS*DKD)    // 524288

#define PSTRIDE 258               // p_s row stride (floats)
#define VSTRIDE 68                // v tile row stride (floats, float4-aligned)
#define XSTRIDE 68                // proj x tile stride
#define WSTRIDE 68                // proj W tile stride (float4-aligned)

// Scratch (no cudaMalloc allowed)
__device__ float    g_qp[NQROWS * DKD];            // [bh*Lq + q][d] f32
__device__ uint32_t g_kph[BHN * DKD * (LK / 2)];   // [bh][d][pair] f16x2 (k-pairs)

__device__ __forceinline__ uint32_t tanh2(uint32_t x) {
    uint32_t y;
    asm("tanh.approx.f16x2 %0, %1;" : "=r"(y) : "r"(x));
    return y;
}
__device__ __forceinline__ uint32_t hadd2u(uint32_t a, uint32_t b) {
    uint32_t d;
    asm("add.f16x2 %0, %1, %2;" : "=r"(d) : "r"(a), "r"(b));
    return d;
}
__device__ __forceinline__ uint32_t hfma2u(uint32_t a, uint32_t b, uint32_t c) {
    uint32_t d;
    asm("fma.rn.f16x2 %0, %1, %2, %3;" : "=r"(d) : "r"(a), "r"(b), "r"(c));
    return d;
}
__device__ __forceinline__ uint32_t pack2(float lo, float hi) {
    __half2 h = __floats2half2_rn(lo, hi);
    return *reinterpret_cast<uint32_t*>(&h);
}
__device__ __forceinline__ uint32_t dup2(float x) { return pack2(x, x); }
__device__ __forceinline__ float2 unpack2(uint32_t v) {
    __half2 h = *reinterpret_cast<__half2*>(&v);
    return __half22float2(h);
}
__device__ __forceinline__ uint16_t f2h(float x) {
    __half h = __float2half_rn(x);
    return *reinterpret_cast<uint16_t*>(&h);
}

// ---------------------------------------------------------------------------
// Kernel 1 (v3): projections, broadcast-blocked.
// Grid 512 x 256 thr. blocks [0,256): qp (f32). [256,512): kp (f16x2 packed).
// Block = 32 rows. Warp = one 8-e group (W LDS.128 = pure broadcast);
// thread = (row = tid&31, eg = tid>>5). 41 issues / 32 MACs.
// ---------------------------------------------------------------------------
__global__ void __launch_bounds__(256)
proj_kernel(const float* __restrict__ xq,
            const float* __restrict__ xk,
            const float* __restrict__ Wq,
            const float* __restrict__ bq,
            const float* __restrict__ Wk,
            const float* __restrict__ bk)
{
    __shared__ float Ws[DKD * WSTRIDE];      // [e][d] padded, 17.4KB
    __shared__ float xs[32 * XSTRIDE];       // [row][d] padded, 8.7KB
    __shared__ uint16_t kst[DKD * 32];       // k path repack: [e][k] f16, 4KB

    const bool is_k = blockIdx.x >= 256;
    const int  blk  = is_k ? (blockIdx.x - 256) : blockIdx.x;
    const float* x  = is_k ? xk : xq;
    const float* W  = is_k ? Wk : Wq;
    const float* bi = is_k ? bk : bq;

    const int tid  = threadIdx.x;            // 0..255
    const int row0 = blk * 32;

    for (int i = tid; i < DKD * DKD; i += 256)
        Ws[(i >> 6) * WSTRIDE + (i & 63)] = W[i];
    for (int i = tid; i < 32 * DKD; i += 256)
        xs[(i >> 6) * XSTRIDE + (i & 63)] = x[row0 * DKD + i];
    __syncthreads();

    const int row = tid & 31;
    const int eg  = tid >> 5;                // warp id = e-group
    const int e0  = eg * 8;

    float acc[8];
    {
        const float4 b0 = *(const float4*)(bi + e0);
        const float4 b1 = *(const float4*)(bi + e0 + 4);
        acc[0] = b0.x; acc[1] = b0.y; acc[2] = b0.z; acc[3] = b0.w;
        acc[4] = b1.x; acc[5] = b1.y; acc[6] = b1.z; acc[7] = b1.w;
    }

#pragma unroll
    for (int d4 = 0; d4 < 16; d4++) {
        const float4 xv = *(const float4*)&xs[row * XSTRIDE + d4 * 4];
#pragma unroll
        for (int ei = 0; ei < 8; ei++) {
            const float4 wv = *(const float4*)&Ws[(e0 + ei) * WSTRIDE + d4 * 4]; // broadcast
            acc[ei] += xv.x * wv.x + xv.y * wv.y + xv.z * wv.z + xv.w * wv.w;
        }
    }

    if (!is_k) {
        float* dst = g_qp + (row0 + row) * DKD + e0;
        *(float4*)dst       = make_float4(acc[0], acc[1], acc[2], acc[3]);
        *(float4*)(dst + 4) = make_float4(acc[4], acc[5], acc[6], acc[7]);
    } else {
        // repack via SMEM: kst[e][k] f16, then coalesced u32-pair stores
#pragma unroll
        for (int ei = 0; ei < 8; ei++)
            kst[(e0 + ei) * 32 + row] = f2h(acc[ei]);
        __syncthreads();

        const int bh = row0 >> 8;
        const int p0 = (row0 & 255) >> 1;          // pair base within [0,128)
        const uint32_t* ksrc = (const uint32_t*)kst;   // [e][16 pairs]
#pragma unroll
        for (int t = 0; t < 4; t++) {
            const int f = tid + t * 256;           // 0..1023
            const int e = f >> 4;
            const int p = f & 15;
            g_kph[bh * (DKD * (LK / 2)) + e * (LK / 2) + p0 + p] = ksrc[e * 16 + p];
        }
    }
}

// ---------------------------------------------------------------------------
// Kernel 2 (fused): scores + softmax -> attn AND output = attn @ v.
// Grid: 1024 CTAs (32 bh x 32 q-tiles). Block: 128 threads (4 warps).
// Phase 1: f16x2 tanh path (MUFU-floor bound). Warp = 2 q rows; lane owns
//   k-pairs {lane, lane+32} per 128-k chunk; f16x2 accum over 8-d groups.
// Phase 2: fp32; v staged as float4 tiles (VSTRIDE 68).
// vs_b dropped (softmax shift-invariant; raw scores not an output).
// ---------------------------------------------------------------------------
__global__ void __launch_bounds__(128, 7)
attn_fused_kernel(const float* __restrict__ vs_w,
                  const float* __restrict__ v,
                  float* __restrict__ out,
                  float* __restrict__ attn_out)
{
    __shared__ float kv[64 * VSTRIDE];     // phase2 v tiles (17.4KB); phase1 aliases 16KB
    __shared__ uint32_t qh2[DKD * 8];      // [d][qr] dup f16x2
    __shared__ uint32_t vswh2[DKD];        // [d] dup f16x2
    __shared__ float p_s[8 * PSTRIDE];     // [qr][k] padded

    uint32_t* kph = (uint32_t*)kv;         // phase1: [d][64 pairs] u32

    const int tid  = threadIdx.x;          // 0..127
    const int lane = tid & 31;
    const int warp = tid >> 5;             // 0..3
    const int bh   = blockIdx.x >> 5;
    const int q0   = (blockIdx.x & 31) * 8;

    if (tid < DKD) vswh2[tid] = dup2(vs_w[tid]);
    {   // build qh2[d][qr] duplicated halves from g_qp
        const int qr = tid & 7;
        const int d4 = tid >> 3;           // 0..15
        const float4 qv = *(const float4*)(g_qp + (bh * LQ + q0 + qr) * DKD + d4 * 4);
        qh2[(d4 * 4 + 0) * 8 + qr] = dup2(qv.x);
        qh2[(d4 * 4 + 1) * 8 + qr] = dup2(qv.y);
        qh2[(d4 * 4 + 2) * 8 + qr] = dup2(qv.z);
        qh2[(d4 * 4 + 3) * 8 + qr] = dup2(qv.w);
    }
    __syncthreads();

    float sc[2][8];
#pragma unroll
    for (int j = 0; j < 2; j++)
#pragma unroll
        for (int i = 0; i < 8; i++) sc[j][i] = 0.f;

    const int qw = warp * 2;

    // ---- Phase 1: scores ----
    for (int c = 0; c < 2; c++) {          // k chunks of 128 (= 64 pairs)
        if (c) __syncthreads();
        {   // stage g_kph chunk -> kph[d][pair]  (raw uint4 copy)
            const uint4* src = (const uint4*)(g_kph + bh * (DKD * (LK / 2)));
            uint4* dst = (uint4*)kph;
#pragma unroll
            for (int t = 0; t < 8; t++) {
                const int f4 = tid + t * 128;        // 0..1023
                const int d  = f4 >> 4;
                const int p4 = f4 & 15;
                dst[f4] = src[d * 32 + c * 16 + p4];
            }
        }
        __syncthreads();

#pragma unroll
        for (int d8 = 0; d8 < 8; d8++) {   // 8-d groups: f16x2 accumulate, flush
            uint32_t a00 = 0u, a01 = 0u, a10 = 0u, a11 = 0u;
#pragma unroll
            for (int dd = 0; dd < 8; dd++) {
                const int d = d8 * 8 + dd;
                const uint32_t kp0 = kph[d * 64 + lane];
                const uint32_t kp1 = kph[d * 64 + 32 + lane];
                const uint32_t q20 = qh2[d * 8 + qw];
                const uint32_t q21 = qh2[d * 8 + qw + 1];
                const uint32_t w2  = vswh2[d];
                a00 = hfma2u(w2, tanh2(hadd2u(q20, kp0)), a00);
                a01 = hfma2u(w2, tanh2(hadd2u(q20, kp1)), a01);
                a10 = hfma2u(w2, tanh2(hadd2u(q21, kp0)), a10);
                a11 = hfma2u(w2, tanh2(hadd2u(q21, kp1)), a11);
            }
            float2 f;
            f = unpack2(a00); sc[0][c*4+0] += f.x; sc[0][c*4+1] += f.y;
            f = unpack2(a01); sc[0][c*4+2] += f.x; sc[0][c*4+3] += f.y;
            f = unpack2(a10); sc[1][c*4+0] += f.x; sc[1][c*4+1] += f.y;
            f = unpack2(a11); sc[1][c*4+2] += f.x; sc[1][c*4+3] += f.y;
        }
    }
    // lane's k for sc[j][c*4 + pi*2 + h] = c*128 + pi*64 + lane*2 + h

    // ---- softmax per q row ----
#pragma unroll
    for (int j = 0; j < 2; j++) {
        float m = sc[j][0];
#pragma unroll
        for (int i = 1; i < 8; i++) m = fmaxf(m, sc[j][i]);
#pragma unroll
        for (int o = 16; o > 0; o >>= 1)
            m = fmaxf(m, __shfl_xor_sync(0xffffffffu, m, o));

        float p[8];
        float s = 0.f;
#pragma unroll
        for (int i = 0; i < 8; i++) { p[i] = __expf(sc[j][i] - m); s += p[i]; }
#pragma unroll
        for (int o = 16; o > 0; o >>= 1)
            s += __shfl_xor_sync(0xffffffffu, s, o);

        const float inv = 1.0f / s;
        const int qr = qw + j;
        float* dst = attn_out + (bh * LQ + q0 + qr) * LK;
#pragma unroll
        for (int c = 0; c < 2; c++)
#pragma unroll
            for (int pi = 0; pi < 2; pi++) {
                const float2 pv = make_float2(p[c*4+pi*2] * inv, p[c*4+pi*2+1] * inv);
                const int kb = c * 128 + pi * 64 + lane * 2;
                *(float2*)&dst[kb]                 = pv;
                *(float2*)&p_s[qr * PSTRIDE + kb]  = pv;
            }
    }
    __syncthreads();

    // ---- Phase 2: out[q][d] = sum_k p[q][k] * v[k][d]  (fp32) ----
    const int q  = tid & 7;
    const int dg = tid >> 3;               // 0..15 -> d = dg*4 .. dg*4+3

    float acc[4];
#pragma unroll
    for (int i = 0; i < 4; i++) acc[i] = 0.f;

    for (int c = 0; c < 4; c++) {          // v chunks of 64 k-rows
        if (c) __syncthreads();
        {   // stage v chunk: 1024 float4 / 128 thr = 8 each
            const float4* src = (const float4*)(v + (bh * LK + c * 64) * DKD);
#pragma unroll
            for (int t = 0; t < 8; t++) {
                const int f  = tid + t * 128;      // float4 index 0..1023
                const int k  = f >> 4;
                const int d4 = f & 15;
                *(float4*)&kv[k * VSTRIDE + d4 * 4] = src[f];
            }
        }
        __syncthreads();

#pragma unroll 4
        for (int kk = 0; kk < 64; kk++) {
            const float a   = p_s[q * PSTRIDE + c * 64 + kk];
            const float4 vk = *(const float4*)&kv[kk * VSTRIDE + dg * 4];
            acc[0] += a * vk.x; acc[1] += a * vk.y;
            acc[2] += a * vk.z; acc[3] += a * vk.w;
        }
    }

    float* od = out + (bh * LQ + q0 + q) * DKD + dg * 4;
    *(float4*)od = make_float4(acc[0], acc[1], acc[2], acc[3]);
}

// ---------------------------------------------------------------------------
extern "C" void kernel_launch(void* const* d_in, const int* in_sizes, int n_in,
                              void* d_out, int out_size)
{
    (void)in_sizes; (void)n_in; (void)out_size;
    const float* q    = (const float*)d_in[0];
    const float* k    = (const float*)d_in[1];
    const float* v    = (const float*)d_in[2];
    const float* Wq_w = (const float*)d_in[3];
    const float* Wq_b = (const float*)d_in[4];
    const float* Wk_w = (const float*)d_in[5];
    const float* Wk_b = (const float*)d_in[6];
    const float* vs_w = (const float*)d_in[7];
    // d_in[8] = vs_b: unused (softmax shift-invariance; scores not an output)

    float* out  = (float*)d_out;            // [B,H,Lq,Dk]
    float* attn = out + OUT_ELEMS;          // [B,H,Lq,Lk]

    proj_kernel<<<512, 256>>>(q, k, Wq_w, Wq_b, Wk_w, Wk_b);
    attn_fused_kernel<<<BHN * (LQ / 8), 128>>>(vs_w, v, out, attn);
}